// round 2
// baseline (speedup 1.0000x reference)
#include <cuda_runtime.h>
#include <math.h>

#define T_STEPS 4096
#define BATCH   128
#define IN_DIM  96
#define H_DIM   64
#define OUT_DIM 2

// Precomputed input currents: P[t][b][h] = (t==0 ? 0 : x[t-1,b,:] @ W_h[h,:])
__device__ float g_P[(size_t)T_STEPS * BATCH * H_DIM];

// ---------- packed f32x2 helpers ----------
__device__ __forceinline__ void fma2(unsigned long long& d, unsigned long long a, unsigned long long b) {
    asm("fma.rn.f32x2 %0, %1, %2, %0;" : "+l"(d) : "l"(a), "l"(b));
}
__device__ __forceinline__ unsigned long long fma2g(unsigned long long a, unsigned long long b,
                                                    unsigned long long c) {
    unsigned long long d;
    asm("fma.rn.f32x2 %0, %1, %2, %3;" : "=l"(d) : "l"(a), "l"(b), "l"(c));
    return d;
}
__device__ __forceinline__ unsigned long long add2(unsigned long long a, unsigned long long b) {
    unsigned long long d;
    asm("add.rn.f32x2 %0, %1, %2;" : "=l"(d) : "l"(a), "l"(b));
    return d;
}
__device__ __forceinline__ unsigned long long mul2(unsigned long long a, unsigned long long b) {
    unsigned long long d;
    asm("mul.rn.f32x2 %0, %1, %2;" : "=l"(d) : "l"(a), "l"(b));
    return d;
}
__device__ __forceinline__ unsigned long long pack2(float x, float y) {
    unsigned long long r;
    asm("mov.b64 %0, {%1, %2};" : "=l"(r) : "f"(x), "f"(y));
    return r;
}
__device__ __forceinline__ float lo32(unsigned long long v) { return __uint_as_float((unsigned)v); }
__device__ __forceinline__ float hi32(unsigned long long v) { return __uint_as_float((unsigned)(v >> 32)); }

// ============================================================
// Kernel 1: P[g] = (g >= BATCH) ? x[g-BATCH,:] @ W_h.T : 0
// 32 rows x 64 cols per CTA; 128 threads, each 2 rows x 8 cols.
// ============================================================
__global__ __launch_bounds__(128) void precompute_inp(const float* __restrict__ x,
                                                      const float* __restrict__ Wh) {
    __shared__ unsigned long long xp[48][34];  // [k-pair][row]
    __shared__ unsigned long long wp[48][66];  // [k-pair][col]

    const int tid = threadIdx.x;
    const long long row0 = (long long)blockIdx.x * 32;

    // Fill W pairs: wp[kk][c] = (Wh[c][2kk], Wh[c][2kk+1])
    for (int l = tid; l < H_DIM * 48; l += 128) {
        int c = l / 48, kk = l % 48;
        float2 w2 = ((const float2*)(Wh + (size_t)c * IN_DIM))[kk];
        wp[kk][c] = pack2(w2.x, w2.y);
    }
    // Fill x pairs with the 1-step shift (t==0 rows -> zeros)
    for (int l = tid; l < 32 * 48; l += 128) {
        int r = l / 48, kk = l % 48;
        long long g = row0 + r;
        float2 v2 = make_float2(0.f, 0.f);
        if (g >= BATCH) v2 = ((const float2*)(x + (g - BATCH) * IN_DIM))[kk];
        xp[kk][r] = pack2(v2.x, v2.y);
    }
    __syncthreads();

    const int tx = tid & 7, ty = tid >> 3;      // tx: col group, ty: row pair
    const int r0 = ty * 2, c0 = tx * 8;

    unsigned long long acc[2][8];
#pragma unroll
    for (int i = 0; i < 2; i++)
#pragma unroll
        for (int j = 0; j < 8; j++) acc[i][j] = 0ull;

#pragma unroll
    for (int kk = 0; kk < 48; kk++) {
        ulonglong2 a  = *(const ulonglong2*)&xp[kk][r0];
        ulonglong2 b0 = *(const ulonglong2*)&wp[kk][c0];
        ulonglong2 b1 = *(const ulonglong2*)&wp[kk][c0 + 2];
        ulonglong2 b2 = *(const ulonglong2*)&wp[kk][c0 + 4];
        ulonglong2 b3 = *(const ulonglong2*)&wp[kk][c0 + 6];
        fma2(acc[0][0], a.x, b0.x); fma2(acc[0][1], a.x, b0.y);
        fma2(acc[0][2], a.x, b1.x); fma2(acc[0][3], a.x, b1.y);
        fma2(acc[0][4], a.x, b2.x); fma2(acc[0][5], a.x, b2.y);
        fma2(acc[0][6], a.x, b3.x); fma2(acc[0][7], a.x, b3.y);
        fma2(acc[1][0], a.y, b0.x); fma2(acc[1][1], a.y, b0.y);
        fma2(acc[1][2], a.y, b1.x); fma2(acc[1][3], a.y, b1.y);
        fma2(acc[1][4], a.y, b2.x); fma2(acc[1][5], a.y, b2.y);
        fma2(acc[1][6], a.y, b3.x); fma2(acc[1][7], a.y, b3.y);
    }

#pragma unroll
    for (int i = 0; i < 2; i++) {
#pragma unroll
        for (int q = 0; q < 2; q++) {
            float4 o;
            o.x = lo32(acc[i][4 * q + 0]) + hi32(acc[i][4 * q + 0]);
            o.y = lo32(acc[i][4 * q + 1]) + hi32(acc[i][4 * q + 1]);
            o.z = lo32(acc[i][4 * q + 2]) + hi32(acc[i][4 * q + 2]);
            o.w = lo32(acc[i][4 * q + 3]) + hi32(acc[i][4 * q + 3]);
            *(float4*)(g_P + (size_t)(row0 + r0 + i) * H_DIM + c0 + 4 * q) = o;
        }
    }
}

// ============================================================
// Kernel 2: sequential scan. ONE WARP per batch.
//   lane l owns neurons 2l and 2l+1.
//   Spike exchange via __ballot_sync (register-resident masks):
//     pm0 bit l = spike of neuron 2l, pm1 bit l = spike of neuron 2l+1.
//   Recurrent + readout dots are selection-sums over spiking neurons
//   (spikes are binary): per spike one LDS.64 + add.f32x2 each.
//   NO __syncthreads in the 4096-step loop.
// ============================================================
__global__ __launch_bounds__(32, 1) void scan_kernel(const float* __restrict__ V,
                                                     const float* __restrict__ Wo,
                                                     float* __restrict__ out,
                                                     float a_h, float b_h,
                                                     float a_o, float b_o) {
    __shared__ __align__(16) float2 Rp[H_DIM][33];  // Rp[j][l] = (V[2l][j], V[2l+1][j])
    __shared__ float2 Wop[H_DIM];                   // Wop[j]   = (Wo[0][j], Wo[1][j])

    const int lane = threadIdx.x;
    const int b    = blockIdx.x;

    // Fill tables (one-time)
    for (int idx = lane; idx < H_DIM * 32; idx += 32) {
        int j = idx >> 5, l = idx & 31;
        Rp[j][l] = make_float2(V[(size_t)(2 * l) * H_DIM + j],
                               V[(size_t)(2 * l + 1) * H_DIM + j]);
    }
    for (int j = lane; j < H_DIM; j += 32)
        Wop[j] = make_float2(Wo[j], Wo[H_DIM + j]);
    __syncthreads();

    const float omb_h = 1.f - b_h;
    const unsigned long long a_h2  = pack2(a_h, a_h);
    const unsigned long long a_o2  = pack2(a_o, a_o);
    const unsigned long long b_o2  = pack2(b_o, b_o);
    const unsigned long long ombo2 = pack2(1.f - b_o, 1.f - b_o);

    unsigned long long syn2 = 0ull, syno2 = 0ull, memo2 = 0ull;
    float mem0 = 0.f, mem1 = 0.f;

    const int strideP = BATCH * H_DIM;
    const float* p = g_P + (size_t)b * H_DIM + 2 * lane;
    float2 cur[8];
#pragma unroll
    for (int q = 0; q < 8; q++) cur[q] = *(const float2*)(p + (size_t)q * strideP);
    const float* pf = p + (size_t)8 * strideP;

    float* optr = out + (size_t)b * OUT_DIM;

    unsigned pm0 = 0u, pm1 = 0u;

    for (int t = 0; t < T_STEPS; t++) {
        // ---- selection-sum dots over previous spikes (masks uniform across warp) ----
        unsigned long long acc2 = 0ull, acco2 = 0ull;
        unsigned m = pm0;
        while (m) {
            int l2 = __ffs(m) - 1;
            m &= (m - 1);
            int j = 2 * l2;
            float2 r = Rp[j][lane];
            acc2 = add2(acc2, pack2(r.x, r.y));
            float2 w = Wop[j];
            acco2 = add2(acco2, pack2(w.x, w.y));
        }
        m = pm1;
        while (m) {
            int l2 = __ffs(m) - 1;
            m &= (m - 1);
            int j = 2 * l2 + 1;
            float2 r = Rp[j][lane];
            acc2 = add2(acc2, pack2(r.x, r.y));
            float2 w = Wop[j];
            acco2 = add2(acco2, pack2(w.x, w.y));
        }

        // ---- neuron update (2 neurons/lane) ----
        float2 c = cur[t & 7];
        if (t + 8 < T_STEPS) cur[t & 7] = *(const float2*)pf;  // prefetch 8 ahead
        pf += strideP;

        unsigned long long cin = add2(pack2(c.x, c.y), acc2);
        syn2 = fma2g(a_h2, syn2, cin);
        mem0 = fmaf(b_h, mem0, omb_h * lo32(syn2));
        mem1 = fmaf(b_h, mem1, omb_h * hi32(syn2));
        bool s0 = (mem0 > 1.f);
        bool s1 = (mem1 > 1.f);
        mem0 = s0 ? 0.f : mem0;
        mem1 = s1 ? 0.f : mem1;
        pm0 = __ballot_sync(0xffffffffu, s0);
        pm1 = __ballot_sync(0xffffffffu, s1);

        // ---- readout (computed redundantly by all lanes; lane 0 stores) ----
        syno2 = fma2g(a_o2, syno2, acco2);
        memo2 = fma2g(b_o2, memo2, mul2(ombo2, syno2));
        if (lane == 0)
            *(float2*)(optr + (size_t)t * (BATCH * OUT_DIM)) =
                make_float2(lo32(memo2), hi32(memo2));
    }
}

// ============================================================
extern "C" void kernel_launch(void* const* d_in, const int* in_sizes, int n_in,
                              void* d_out, int out_size) {
    const float* x  = (const float*)d_in[0];
    const float* Wh = (const float*)d_in[1];
    const float* V  = (const float*)d_in[2];
    const float* Wo = (const float*)d_in[3];
    float* out = (float*)d_out;

    const double S = log1p(exp(1.0));
    const float a_h = expf((float)(-0.004 / (S * 0.01)));
    const float b_h = expf((float)(-0.004 / (S * 0.02)));
    const float a_o = a_h;
    const float b_o = b_h;

    precompute_inp<<<(T_STEPS * BATCH) / 32, 128>>>(x, Wh);
    scan_kernel<<<BATCH, 32>>>(V, Wo, out, a_h, b_h, a_o, b_o);
}

// round 3
// speedup vs baseline: 1.0027x; 1.0027x over previous
#include <cuda_runtime.h>
#include <math.h>

#define T_STEPS 4096
#define BATCH   128
#define IN_DIM  96
#define H_DIM   64
#define OUT_DIM 2

// Precomputed input currents: P[t][b][h] = (t==0 ? 0 : x[t-1,b,:] @ W_h[h,:])
__device__ float g_P[(size_t)T_STEPS * BATCH * H_DIM];

// ---------- packed f32x2 helpers ----------
__device__ __forceinline__ void fma2(unsigned long long& d, unsigned long long a, unsigned long long b) {
    asm("fma.rn.f32x2 %0, %1, %2, %0;" : "+l"(d) : "l"(a), "l"(b));
}
__device__ __forceinline__ unsigned long long fma2g(unsigned long long a, unsigned long long b,
                                                    unsigned long long c) {
    unsigned long long d;
    asm("fma.rn.f32x2 %0, %1, %2, %3;" : "=l"(d) : "l"(a), "l"(b), "l"(c));
    return d;
}
__device__ __forceinline__ unsigned long long add2(unsigned long long a, unsigned long long b) {
    unsigned long long d;
    asm("add.rn.f32x2 %0, %1, %2;" : "=l"(d) : "l"(a), "l"(b));
    return d;
}
__device__ __forceinline__ unsigned long long mul2(unsigned long long a, unsigned long long b) {
    unsigned long long d;
    asm("mul.rn.f32x2 %0, %1, %2;" : "=l"(d) : "l"(a), "l"(b));
    return d;
}
__device__ __forceinline__ unsigned long long pack2(float x, float y) {
    unsigned long long r;
    asm("mov.b64 %0, {%1, %2};" : "=l"(r) : "f"(x), "f"(y));
    return r;
}
__device__ __forceinline__ float lo32(unsigned long long v) { return __uint_as_float((unsigned)v); }
__device__ __forceinline__ float hi32(unsigned long long v) { return __uint_as_float((unsigned)(v >> 32)); }

// ============================================================
// Kernel 1: P[g] = (g >= BATCH) ? x[g-BATCH,:] @ W_h.T : 0
// 32 rows x 64 cols per CTA; 128 threads, each 2 rows x 8 cols.
// ============================================================
__global__ __launch_bounds__(128) void precompute_inp(const float* __restrict__ x,
                                                      const float* __restrict__ Wh) {
    __shared__ unsigned long long xp[48][34];  // [k-pair][row]
    __shared__ unsigned long long wp[48][66];  // [k-pair][col]

    const int tid = threadIdx.x;
    const long long row0 = (long long)blockIdx.x * 32;

    // Fill W pairs: wp[kk][c] = (Wh[c][2kk], Wh[c][2kk+1])
    for (int l = tid; l < H_DIM * 48; l += 128) {
        int c = l / 48, kk = l % 48;
        float2 w2 = ((const float2*)(Wh + (size_t)c * IN_DIM))[kk];
        wp[kk][c] = pack2(w2.x, w2.y);
    }
    // Fill x pairs with the 1-step shift (t==0 rows -> zeros)
    for (int l = tid; l < 32 * 48; l += 128) {
        int r = l / 48, kk = l % 48;
        long long g = row0 + r;
        float2 v2 = make_float2(0.f, 0.f);
        if (g >= BATCH) v2 = ((const float2*)(x + (g - BATCH) * IN_DIM))[kk];
        xp[kk][r] = pack2(v2.x, v2.y);
    }
    __syncthreads();

    const int tx = tid & 7, ty = tid >> 3;      // tx: col group, ty: row pair
    const int r0 = ty * 2, c0 = tx * 8;

    unsigned long long acc[2][8];
#pragma unroll
    for (int i = 0; i < 2; i++)
#pragma unroll
        for (int j = 0; j < 8; j++) acc[i][j] = 0ull;

#pragma unroll
    for (int kk = 0; kk < 48; kk++) {
        ulonglong2 a  = *(const ulonglong2*)&xp[kk][r0];
        ulonglong2 b0 = *(const ulonglong2*)&wp[kk][c0];
        ulonglong2 b1 = *(const ulonglong2*)&wp[kk][c0 + 2];
        ulonglong2 b2 = *(const ulonglong2*)&wp[kk][c0 + 4];
        ulonglong2 b3 = *(const ulonglong2*)&wp[kk][c0 + 6];
        fma2(acc[0][0], a.x, b0.x); fma2(acc[0][1], a.x, b0.y);
        fma2(acc[0][2], a.x, b1.x); fma2(acc[0][3], a.x, b1.y);
        fma2(acc[0][4], a.x, b2.x); fma2(acc[0][5], a.x, b2.y);
        fma2(acc[0][6], a.x, b3.x); fma2(acc[0][7], a.x, b3.y);
        fma2(acc[1][0], a.y, b0.x); fma2(acc[1][1], a.y, b0.y);
        fma2(acc[1][2], a.y, b1.x); fma2(acc[1][3], a.y, b1.y);
        fma2(acc[1][4], a.y, b2.x); fma2(acc[1][5], a.y, b2.y);
        fma2(acc[1][6], a.y, b3.x); fma2(acc[1][7], a.y, b3.y);
    }

#pragma unroll
    for (int i = 0; i < 2; i++) {
#pragma unroll
        for (int q = 0; q < 2; q++) {
            float4 o;
            o.x = lo32(acc[i][4 * q + 0]) + hi32(acc[i][4 * q + 0]);
            o.y = lo32(acc[i][4 * q + 1]) + hi32(acc[i][4 * q + 1]);
            o.z = lo32(acc[i][4 * q + 2]) + hi32(acc[i][4 * q + 2]);
            o.w = lo32(acc[i][4 * q + 3]) + hi32(acc[i][4 * q + 3]);
            *(float4*)(g_P + (size_t)(row0 + r0 + i) * H_DIM + c0 + 4 * q) = o;
        }
    }
}

// ============================================================
// Kernel 2: sequential scan. ONE WARP per batch.
//   lane l owns neurons 2l and 2l+1.
//   Spike exchange via __ballot_sync (register-resident masks):
//     pm0 bit l = spike of neuron 2l, pm1 bit l = spike of neuron 2l+1.
//   Recurrent + readout dots are selection-sums over spiking neurons
//   (spikes are binary): per spike one LDS.64 + add.f32x2 each.
//   NO __syncthreads in the 4096-step loop.
// ============================================================
__global__ __launch_bounds__(32, 1) void scan_kernel(const float* __restrict__ V,
                                                     const float* __restrict__ Wo,
                                                     float* __restrict__ out,
                                                     float a_h, float b_h,
                                                     float a_o, float b_o) {
    __shared__ __align__(16) float2 Rp[H_DIM][33];  // Rp[j][l] = (V[2l][j], V[2l+1][j])
    __shared__ float2 Wop[H_DIM];                   // Wop[j]   = (Wo[0][j], Wo[1][j])

    const int lane = threadIdx.x;
    const int b    = blockIdx.x;

    // Fill tables (one-time)
    for (int idx = lane; idx < H_DIM * 32; idx += 32) {
        int j = idx >> 5, l = idx & 31;
        Rp[j][l] = make_float2(V[(size_t)(2 * l) * H_DIM + j],
                               V[(size_t)(2 * l + 1) * H_DIM + j]);
    }
    for (int j = lane; j < H_DIM; j += 32)
        Wop[j] = make_float2(Wo[j], Wo[H_DIM + j]);
    __syncthreads();

    const float omb_h = 1.f - b_h;
    const unsigned long long a_h2  = pack2(a_h, a_h);
    const unsigned long long a_o2  = pack2(a_o, a_o);
    const unsigned long long b_o2  = pack2(b_o, b_o);
    const unsigned long long ombo2 = pack2(1.f - b_o, 1.f - b_o);

    unsigned long long syn2 = 0ull, syno2 = 0ull, memo2 = 0ull;
    float mem0 = 0.f, mem1 = 0.f;

    const int strideP = BATCH * H_DIM;
    const float* p = g_P + (size_t)b * H_DIM + 2 * lane;
    float2 cur[8];
#pragma unroll
    for (int q = 0; q < 8; q++) cur[q] = *(const float2*)(p + (size_t)q * strideP);
    const float* pf = p + (size_t)8 * strideP;

    float* optr = out + (size_t)b * OUT_DIM;

    unsigned pm0 = 0u, pm1 = 0u;

    for (int t = 0; t < T_STEPS; t++) {
        // ---- selection-sum dots over previous spikes (masks uniform across warp) ----
        unsigned long long acc2 = 0ull, acco2 = 0ull;
        unsigned m = pm0;
        while (m) {
            int l2 = __ffs(m) - 1;
            m &= (m - 1);
            int j = 2 * l2;
            float2 r = Rp[j][lane];
            acc2 = add2(acc2, pack2(r.x, r.y));
            float2 w = Wop[j];
            acco2 = add2(acco2, pack2(w.x, w.y));
        }
        m = pm1;
        while (m) {
            int l2 = __ffs(m) - 1;
            m &= (m - 1);
            int j = 2 * l2 + 1;
            float2 r = Rp[j][lane];
            acc2 = add2(acc2, pack2(r.x, r.y));
            float2 w = Wop[j];
            acco2 = add2(acco2, pack2(w.x, w.y));
        }

        // ---- neuron update (2 neurons/lane) ----
        float2 c = cur[t & 7];
        if (t + 8 < T_STEPS) cur[t & 7] = *(const float2*)pf;  // prefetch 8 ahead
        pf += strideP;

        unsigned long long cin = add2(pack2(c.x, c.y), acc2);
        syn2 = fma2g(a_h2, syn2, cin);
        mem0 = fmaf(b_h, mem0, omb_h * lo32(syn2));
        mem1 = fmaf(b_h, mem1, omb_h * hi32(syn2));
        bool s0 = (mem0 > 1.f);
        bool s1 = (mem1 > 1.f);
        mem0 = s0 ? 0.f : mem0;
        mem1 = s1 ? 0.f : mem1;
        pm0 = __ballot_sync(0xffffffffu, s0);
        pm1 = __ballot_sync(0xffffffffu, s1);

        // ---- readout (computed redundantly by all lanes; lane 0 stores) ----
        syno2 = fma2g(a_o2, syno2, acco2);
        memo2 = fma2g(b_o2, memo2, mul2(ombo2, syno2));
        if (lane == 0)
            *(float2*)(optr + (size_t)t * (BATCH * OUT_DIM)) =
                make_float2(lo32(memo2), hi32(memo2));
    }
}

// ============================================================
extern "C" void kernel_launch(void* const* d_in, const int* in_sizes, int n_in,
                              void* d_out, int out_size) {
    const float* x  = (const float*)d_in[0];
    const float* Wh = (const float*)d_in[1];
    const float* V  = (const float*)d_in[2];
    const float* Wo = (const float*)d_in[3];
    float* out = (float*)d_out;

    const double S = log1p(exp(1.0));
    const float a_h = expf((float)(-0.004 / (S * 0.01)));
    const float b_h = expf((float)(-0.004 / (S * 0.02)));
    const float a_o = a_h;
    const float b_o = b_h;

    precompute_inp<<<(T_STEPS * BATCH) / 32, 128>>>(x, Wh);
    scan_kernel<<<BATCH, 32>>>(V, Wo, out, a_h, b_h, a_o, b_o);
}

// round 4
// speedup vs baseline: 1.0943x; 1.0914x over previous
#include <cuda_runtime.h>
#include <math.h>

#define T_STEPS 4096
#define BATCH   128
#define IN_DIM  96
#define H_DIM   64
#define OUT_DIM 2

typedef unsigned long long ull;

// Precomputed input currents: P[t][b][h] = (t==0 ? 0 : x[t-1,b,:] @ W_h[h,:])
__device__ float g_P[(size_t)T_STEPS * BATCH * H_DIM];

// ---------- packed f32x2 helpers ----------
__device__ __forceinline__ void fma2(ull& d, ull a, ull b) {
    asm("fma.rn.f32x2 %0, %1, %2, %0;" : "+l"(d) : "l"(a), "l"(b));
}
__device__ __forceinline__ ull fma2g(ull a, ull b, ull c) {
    ull d;
    asm("fma.rn.f32x2 %0, %1, %2, %3;" : "=l"(d) : "l"(a), "l"(b), "l"(c));
    return d;
}
__device__ __forceinline__ ull add2(ull a, ull b) {
    ull d;
    asm("add.rn.f32x2 %0, %1, %2;" : "=l"(d) : "l"(a), "l"(b));
    return d;
}
__device__ __forceinline__ ull mul2(ull a, ull b) {
    ull d;
    asm("mul.rn.f32x2 %0, %1, %2;" : "=l"(d) : "l"(a), "l"(b));
    return d;
}
__device__ __forceinline__ ull pack2(float x, float y) {
    ull r;
    asm("mov.b64 %0, {%1, %2};" : "=l"(r) : "f"(x), "f"(y));
    return r;
}
__device__ __forceinline__ float lo32(ull v) { return __uint_as_float((unsigned)v); }
__device__ __forceinline__ float hi32(ull v) { return __uint_as_float((unsigned)(v >> 32)); }

// ============================================================
// Kernel 1: P[g] = (g >= BATCH) ? x[g-BATCH,:] @ W_h.T : 0
// 32 rows x 64 cols per CTA; 128 threads, each 2 rows x 8 cols.
// ============================================================
__global__ __launch_bounds__(128) void precompute_inp(const float* __restrict__ x,
                                                      const float* __restrict__ Wh) {
    __shared__ ull xp[48][34];  // [k-pair][row]
    __shared__ ull wp[48][66];  // [k-pair][col]

    const int tid = threadIdx.x;
    const long long row0 = (long long)blockIdx.x * 32;

    for (int l = tid; l < H_DIM * 48; l += 128) {
        int c = l / 48, kk = l % 48;
        float2 w2 = ((const float2*)(Wh + (size_t)c * IN_DIM))[kk];
        wp[kk][c] = pack2(w2.x, w2.y);
    }
    for (int l = tid; l < 32 * 48; l += 128) {
        int r = l / 48, kk = l % 48;
        long long g = row0 + r;
        float2 v2 = make_float2(0.f, 0.f);
        if (g >= BATCH) v2 = ((const float2*)(x + (g - BATCH) * IN_DIM))[kk];
        xp[kk][r] = pack2(v2.x, v2.y);
    }
    __syncthreads();

    const int tx = tid & 7, ty = tid >> 3;
    const int r0 = ty * 2, c0 = tx * 8;

    ull acc[2][8];
#pragma unroll
    for (int i = 0; i < 2; i++)
#pragma unroll
        for (int j = 0; j < 8; j++) acc[i][j] = 0ull;

#pragma unroll
    for (int kk = 0; kk < 48; kk++) {
        ulonglong2 a  = *(const ulonglong2*)&xp[kk][r0];
        ulonglong2 b0 = *(const ulonglong2*)&wp[kk][c0];
        ulonglong2 b1 = *(const ulonglong2*)&wp[kk][c0 + 2];
        ulonglong2 b2 = *(const ulonglong2*)&wp[kk][c0 + 4];
        ulonglong2 b3 = *(const ulonglong2*)&wp[kk][c0 + 6];
        fma2(acc[0][0], a.x, b0.x); fma2(acc[0][1], a.x, b0.y);
        fma2(acc[0][2], a.x, b1.x); fma2(acc[0][3], a.x, b1.y);
        fma2(acc[0][4], a.x, b2.x); fma2(acc[0][5], a.x, b2.y);
        fma2(acc[0][6], a.x, b3.x); fma2(acc[0][7], a.x, b3.y);
        fma2(acc[1][0], a.y, b0.x); fma2(acc[1][1], a.y, b0.y);
        fma2(acc[1][2], a.y, b1.x); fma2(acc[1][3], a.y, b1.y);
        fma2(acc[1][4], a.y, b2.x); fma2(acc[1][5], a.y, b2.y);
        fma2(acc[1][6], a.y, b3.x); fma2(acc[1][7], a.y, b3.y);
    }

#pragma unroll
    for (int i = 0; i < 2; i++) {
#pragma unroll
        for (int q = 0; q < 2; q++) {
            float4 o;
            o.x = lo32(acc[i][4 * q + 0]) + hi32(acc[i][4 * q + 0]);
            o.y = lo32(acc[i][4 * q + 1]) + hi32(acc[i][4 * q + 1]);
            o.z = lo32(acc[i][4 * q + 2]) + hi32(acc[i][4 * q + 2]);
            o.w = lo32(acc[i][4 * q + 3]) + hi32(acc[i][4 * q + 3]);
            *(float4*)(g_P + (size_t)(row0 + r0 + i) * H_DIM + c0 + 4 * q) = o;
        }
    }
}

// ============================================================
// Kernel 2: sequential scan. ONE WARP per batch. Lane l owns
// neurons 2l, 2l+1. Spikes live in two ballot masks (pm0=even,
// pm1=odd neurons). Recurrent dot = FIXED-COST nibble-LUT sum:
//   lutH[p][v][lane] = sum of V columns selected by nibble v at
//   position p  (p<8: nibbles of pm0, p>=8: nibbles of pm1).
// Readout dot = byte-LUT (uniform across lanes, broadcast LDS).
// No branches, no __syncthreads, no data-dependent loops.
// ============================================================
__global__ __launch_bounds__(32, 1) void scan_kernel(const float* __restrict__ V,
                                                     const float* __restrict__ Wo,
                                                     float* __restrict__ out,
                                                     float a_h, float b_h,
                                                     float a_o, float b_o) {
    extern __shared__ __align__(16) char smem[];
    float2* lutH = (float2*)smem;                    // [16][16][32] = 64 KB
    float2* lutO = (float2*)(smem + 16 * 16 * 32 * 8);  // [8][256]  = 16 KB

    const int lane = threadIdx.x;
    const int b    = blockIdx.x;

    // ---- build hidden LUT ----
#pragma unroll
    for (int p = 0; p < 16; p++) {
        float2 v2[4];
#pragma unroll
        for (int i = 0; i < 4; i++) {
            int j = (p < 8) ? (8 * p + 2 * i) : (8 * (p - 8) + 1 + 2 * i);
            v2[i].x = V[(size_t)(2 * lane) * H_DIM + j];
            v2[i].y = V[(size_t)(2 * lane + 1) * H_DIM + j];
        }
#pragma unroll
        for (int v = 0; v < 16; v++) {
            float2 s = make_float2(0.f, 0.f);
            if (v & 1) { s.x += v2[0].x; s.y += v2[0].y; }
            if (v & 2) { s.x += v2[1].x; s.y += v2[1].y; }
            if (v & 4) { s.x += v2[2].x; s.y += v2[2].y; }
            if (v & 8) { s.x += v2[3].x; s.y += v2[3].y; }
            lutH[(p * 16 + v) * 32 + lane] = s;
        }
    }
    // ---- build readout LUT (byte-indexed) ----
    for (int idx = lane; idx < 8 * 256; idx += 32) {
        int p = idx >> 8, v = idx & 255;
        float2 s = make_float2(0.f, 0.f);
#pragma unroll
        for (int i = 0; i < 8; i++) {
            if (v & (1 << i)) {
                int j = (p < 4) ? 2 * (8 * p + i) : 2 * (8 * (p - 4) + i) + 1;
                s.x += Wo[j];
                s.y += Wo[H_DIM + j];
            }
        }
        lutO[idx] = s;
    }
    __syncwarp();

    const float omb_h = 1.f - b_h;
    const ull a_h2  = pack2(a_h, a_h);
    const ull a_o2  = pack2(a_o, a_o);
    const ull b_o2  = pack2(b_o, b_o);
    const ull ombo2 = pack2(1.f - b_o, 1.f - b_o);

    ull syn2 = 0ull, syno2 = 0ull, memo2 = 0ull;
    float mem0 = 0.f, mem1 = 0.f;

    const int strideP = BATCH * H_DIM;
    const float* p = g_P + (size_t)b * H_DIM + 2 * lane;
    float2 cur[8];
#pragma unroll
    for (int q = 0; q < 8; q++) cur[q] = *(const float2*)(p + (size_t)q * strideP);
    const float* pf = p + (size_t)8 * strideP;

    float* optr = out + (size_t)b * OUT_DIM;

    unsigned pm0 = 0u, pm1 = 0u;

#pragma unroll 2
    for (int t = 0; t < T_STEPS; t++) {
        // ---- hidden recurrent dot: 16 nibble lookups, fixed cost ----
        ull h[16];
#pragma unroll
        for (int q = 0; q < 8; q++) {
            unsigned v0 = (pm0 >> (4 * q)) & 15u;
            unsigned v1 = (pm1 >> (4 * q)) & 15u;
            h[q]     = *(const ull*)&lutH[(q * 16 + v0) * 32 + lane];
            h[8 + q] = *(const ull*)&lutH[((8 + q) * 16 + v1) * 32 + lane];
        }
#pragma unroll
        for (int st = 8; st >= 1; st >>= 1)
#pragma unroll
            for (int q = 0; q < st; q++) h[q] = add2(h[q], h[q + st]);
        const ull acc2 = h[0];

        // ---- readout dot: 8 byte lookups (broadcast) ----
        ull r[8];
#pragma unroll
        for (int q = 0; q < 4; q++) {
            unsigned u0 = (pm0 >> (8 * q)) & 255u;
            unsigned u1 = (pm1 >> (8 * q)) & 255u;
            r[q]     = *(const ull*)&lutO[q * 256 + u0];
            r[4 + q] = *(const ull*)&lutO[(4 + q) * 256 + u1];
        }
#pragma unroll
        for (int st = 4; st >= 1; st >>= 1)
#pragma unroll
            for (int q = 0; q < st; q++) r[q] = add2(r[q], r[q + st]);
        const ull acco2 = r[0];

        // ---- neuron state update (2 neurons/lane) ----
        float2 c = cur[t & 7];
        if (t + 8 < T_STEPS) cur[t & 7] = *(const float2*)pf;  // prefetch 8 ahead
        pf += strideP;

        syn2 = fma2g(a_h2, syn2, add2(pack2(c.x, c.y), acc2));
        mem0 = fmaf(b_h, mem0, omb_h * lo32(syn2));
        mem1 = fmaf(b_h, mem1, omb_h * hi32(syn2));
        bool s0 = (mem0 > 1.f);
        bool s1 = (mem1 > 1.f);
        mem0 = s0 ? 0.f : mem0;
        mem1 = s1 ? 0.f : mem1;
        pm0 = __ballot_sync(0xffffffffu, s0);
        pm1 = __ballot_sync(0xffffffffu, s1);

        // ---- readout state + store (lane 0) ----
        syno2 = fma2g(a_o2, syno2, acco2);
        memo2 = fma2g(b_o2, memo2, mul2(ombo2, syno2));
        if (lane == 0)
            *(float2*)(optr + (size_t)t * (BATCH * OUT_DIM)) =
                make_float2(lo32(memo2), hi32(memo2));
    }
}

// ============================================================
extern "C" void kernel_launch(void* const* d_in, const int* in_sizes, int n_in,
                              void* d_out, int out_size) {
    const float* x  = (const float*)d_in[0];
    const float* Wh = (const float*)d_in[1];
    const float* V  = (const float*)d_in[2];
    const float* Wo = (const float*)d_in[3];
    float* out = (float*)d_out;

    const double S = log1p(exp(1.0));
    const float a_h = expf((float)(-0.004 / (S * 0.01)));
    const float b_h = expf((float)(-0.004 / (S * 0.02)));
    const float a_o = a_h;
    const float b_o = b_h;

    const int smem_bytes = 16 * 16 * 32 * 8 + 8 * 256 * 8;  // 80 KB
    cudaFuncSetAttribute(scan_kernel, cudaFuncAttributeMaxDynamicSharedMemorySize,
                         smem_bytes);

    precompute_inp<<<(T_STEPS * BATCH) / 32, 128>>>(x, Wh);
    scan_kernel<<<BATCH, 32, smem_bytes>>>(V, Wo, out, a_h, b_h, a_o, b_o);
}

// round 5
// speedup vs baseline: 1.0946x; 1.0002x over previous
#include <cuda_runtime.h>
#include <math.h>

#define T_STEPS 4096
#define BATCH   128
#define IN_DIM  96
#define H_DIM   64
#define OUT_DIM 2

typedef unsigned long long ull;

// Precomputed input currents: P[t][b][h] = (t==0 ? 0 : x[t-1,b,:] @ W_h[h,:])
__device__ float g_P[(size_t)T_STEPS * BATCH * H_DIM];

// ---------- packed f32x2 helpers ----------
__device__ __forceinline__ void fma2(ull& d, ull a, ull b) {
    asm("fma.rn.f32x2 %0, %1, %2, %0;" : "+l"(d) : "l"(a), "l"(b));
}
__device__ __forceinline__ ull fma2g(ull a, ull b, ull c) {
    ull d;
    asm("fma.rn.f32x2 %0, %1, %2, %3;" : "=l"(d) : "l"(a), "l"(b), "l"(c));
    return d;
}
__device__ __forceinline__ ull add2(ull a, ull b) {
    ull d;
    asm("add.rn.f32x2 %0, %1, %2;" : "=l"(d) : "l"(a), "l"(b));
    return d;
}
__device__ __forceinline__ ull mul2(ull a, ull b) {
    ull d;
    asm("mul.rn.f32x2 %0, %1, %2;" : "=l"(d) : "l"(a), "l"(b));
    return d;
}
__device__ __forceinline__ ull pack2(float x, float y) {
    ull r;
    asm("mov.b64 %0, {%1, %2};" : "=l"(r) : "f"(x), "f"(y));
    return r;
}
__device__ __forceinline__ float lo32(ull v) { return __uint_as_float((unsigned)v); }
__device__ __forceinline__ float hi32(ull v) { return __uint_as_float((unsigned)(v >> 32)); }

// ============================================================
// Kernel 1: P[g] = (g >= BATCH) ? x[g-BATCH,:] @ W_h.T : 0
// 32 rows x 64 cols per CTA; 128 threads, each 2 rows x 8 cols.
// ============================================================
__global__ __launch_bounds__(128) void precompute_inp(const float* __restrict__ x,
                                                      const float* __restrict__ Wh) {
    __shared__ ull xp[48][34];  // [k-pair][row]
    __shared__ ull wp[48][66];  // [k-pair][col]

    const int tid = threadIdx.x;
    const long long row0 = (long long)blockIdx.x * 32;

    for (int l = tid; l < H_DIM * 48; l += 128) {
        int c = l / 48, kk = l % 48;
        float2 w2 = ((const float2*)(Wh + (size_t)c * IN_DIM))[kk];
        wp[kk][c] = pack2(w2.x, w2.y);
    }
    for (int l = tid; l < 32 * 48; l += 128) {
        int r = l / 48, kk = l % 48;
        long long g = row0 + r;
        float2 v2 = make_float2(0.f, 0.f);
        if (g >= BATCH) v2 = ((const float2*)(x + (g - BATCH) * IN_DIM))[kk];
        xp[kk][r] = pack2(v2.x, v2.y);
    }
    __syncthreads();

    const int tx = tid & 7, ty = tid >> 3;
    const int r0 = ty * 2, c0 = tx * 8;

    ull acc[2][8];
#pragma unroll
    for (int i = 0; i < 2; i++)
#pragma unroll
        for (int j = 0; j < 8; j++) acc[i][j] = 0ull;

#pragma unroll
    for (int kk = 0; kk < 48; kk++) {
        ulonglong2 a  = *(const ulonglong2*)&xp[kk][r0];
        ulonglong2 b0 = *(const ulonglong2*)&wp[kk][c0];
        ulonglong2 b1 = *(const ulonglong2*)&wp[kk][c0 + 2];
        ulonglong2 b2 = *(const ulonglong2*)&wp[kk][c0 + 4];
        ulonglong2 b3 = *(const ulonglong2*)&wp[kk][c0 + 6];
        fma2(acc[0][0], a.x, b0.x); fma2(acc[0][1], a.x, b0.y);
        fma2(acc[0][2], a.x, b1.x); fma2(acc[0][3], a.x, b1.y);
        fma2(acc[0][4], a.x, b2.x); fma2(acc[0][5], a.x, b2.y);
        fma2(acc[0][6], a.x, b3.x); fma2(acc[0][7], a.x, b3.y);
        fma2(acc[1][0], a.y, b0.x); fma2(acc[1][1], a.y, b0.y);
        fma2(acc[1][2], a.y, b1.x); fma2(acc[1][3], a.y, b1.y);
        fma2(acc[1][4], a.y, b2.x); fma2(acc[1][5], a.y, b2.y);
        fma2(acc[1][6], a.y, b3.x); fma2(acc[1][7], a.y, b3.y);
    }

#pragma unroll
    for (int i = 0; i < 2; i++) {
#pragma unroll
        for (int q = 0; q < 2; q++) {
            float4 o;
            o.x = lo32(acc[i][4 * q + 0]) + hi32(acc[i][4 * q + 0]);
            o.y = lo32(acc[i][4 * q + 1]) + hi32(acc[i][4 * q + 1]);
            o.z = lo32(acc[i][4 * q + 2]) + hi32(acc[i][4 * q + 2]);
            o.w = lo32(acc[i][4 * q + 3]) + hi32(acc[i][4 * q + 3]);
            *(float4*)(g_P + (size_t)(row0 + r0 + i) * H_DIM + c0 + 4 * q) = o;
        }
    }
}

// ============================================================
// Kernel 2: sequential scan. ONE WARP per batch. Lane l owns
// neurons 2l, 2l+1. Spikes live in two ballot masks (pm0=even,
// pm1=odd neurons). Recurrent dot = FIXED-COST nibble-LUT sum:
//   lutH[p][v][lane] = sum of V columns selected by nibble v at
//   position p  (p<8: nibbles of pm0, p>=8: nibbles of pm1).
// Readout dot = byte-LUT (uniform across lanes, broadcast LDS).
// No branches, no __syncthreads, no data-dependent loops.
// ============================================================
__global__ __launch_bounds__(32, 1) void scan_kernel(const float* __restrict__ V,
                                                     const float* __restrict__ Wo,
                                                     float* __restrict__ out,
                                                     float a_h, float b_h,
                                                     float a_o, float b_o) {
    extern __shared__ __align__(16) char smem[];
    float2* lutH = (float2*)smem;                    // [16][16][32] = 64 KB
    float2* lutO = (float2*)(smem + 16 * 16 * 32 * 8);  // [8][256]  = 16 KB

    const int lane = threadIdx.x;
    const int b    = blockIdx.x;

    // ---- build hidden LUT ----
#pragma unroll
    for (int p = 0; p < 16; p++) {
        float2 v2[4];
#pragma unroll
        for (int i = 0; i < 4; i++) {
            int j = (p < 8) ? (8 * p + 2 * i) : (8 * (p - 8) + 1 + 2 * i);
            v2[i].x = V[(size_t)(2 * lane) * H_DIM + j];
            v2[i].y = V[(size_t)(2 * lane + 1) * H_DIM + j];
        }
#pragma unroll
        for (int v = 0; v < 16; v++) {
            float2 s = make_float2(0.f, 0.f);
            if (v & 1) { s.x += v2[0].x; s.y += v2[0].y; }
            if (v & 2) { s.x += v2[1].x; s.y += v2[1].y; }
            if (v & 4) { s.x += v2[2].x; s.y += v2[2].y; }
            if (v & 8) { s.x += v2[3].x; s.y += v2[3].y; }
            lutH[(p * 16 + v) * 32 + lane] = s;
        }
    }
    // ---- build readout LUT (byte-indexed) ----
    for (int idx = lane; idx < 8 * 256; idx += 32) {
        int p = idx >> 8, v = idx & 255;
        float2 s = make_float2(0.f, 0.f);
#pragma unroll
        for (int i = 0; i < 8; i++) {
            if (v & (1 << i)) {
                int j = (p < 4) ? 2 * (8 * p + i) : 2 * (8 * (p - 4) + i) + 1;
                s.x += Wo[j];
                s.y += Wo[H_DIM + j];
            }
        }
        lutO[idx] = s;
    }
    __syncwarp();

    const float omb_h = 1.f - b_h;
    const ull a_h2  = pack2(a_h, a_h);
    const ull a_o2  = pack2(a_o, a_o);
    const ull b_o2  = pack2(b_o, b_o);
    const ull ombo2 = pack2(1.f - b_o, 1.f - b_o);

    ull syn2 = 0ull, syno2 = 0ull, memo2 = 0ull;
    float mem0 = 0.f, mem1 = 0.f;

    const int strideP = BATCH * H_DIM;
    const float* p = g_P + (size_t)b * H_DIM + 2 * lane;
    float2 cur[8];
#pragma unroll
    for (int q = 0; q < 8; q++) cur[q] = *(const float2*)(p + (size_t)q * strideP);
    const float* pf = p + (size_t)8 * strideP;

    float* optr = out + (size_t)b * OUT_DIM;

    unsigned pm0 = 0u, pm1 = 0u;

#pragma unroll 2
    for (int t = 0; t < T_STEPS; t++) {
        // ---- hidden recurrent dot: 16 nibble lookups, fixed cost ----
        ull h[16];
#pragma unroll
        for (int q = 0; q < 8; q++) {
            unsigned v0 = (pm0 >> (4 * q)) & 15u;
            unsigned v1 = (pm1 >> (4 * q)) & 15u;
            h[q]     = *(const ull*)&lutH[(q * 16 + v0) * 32 + lane];
            h[8 + q] = *(const ull*)&lutH[((8 + q) * 16 + v1) * 32 + lane];
        }
#pragma unroll
        for (int st = 8; st >= 1; st >>= 1)
#pragma unroll
            for (int q = 0; q < st; q++) h[q] = add2(h[q], h[q + st]);
        const ull acc2 = h[0];

        // ---- readout dot: 8 byte lookups (broadcast) ----
        ull r[8];
#pragma unroll
        for (int q = 0; q < 4; q++) {
            unsigned u0 = (pm0 >> (8 * q)) & 255u;
            unsigned u1 = (pm1 >> (8 * q)) & 255u;
            r[q]     = *(const ull*)&lutO[q * 256 + u0];
            r[4 + q] = *(const ull*)&lutO[(4 + q) * 256 + u1];
        }
#pragma unroll
        for (int st = 4; st >= 1; st >>= 1)
#pragma unroll
            for (int q = 0; q < st; q++) r[q] = add2(r[q], r[q + st]);
        const ull acco2 = r[0];

        // ---- neuron state update (2 neurons/lane) ----
        float2 c = cur[t & 7];
        if (t + 8 < T_STEPS) cur[t & 7] = *(const float2*)pf;  // prefetch 8 ahead
        pf += strideP;

        syn2 = fma2g(a_h2, syn2, add2(pack2(c.x, c.y), acc2));
        mem0 = fmaf(b_h, mem0, omb_h * lo32(syn2));
        mem1 = fmaf(b_h, mem1, omb_h * hi32(syn2));
        bool s0 = (mem0 > 1.f);
        bool s1 = (mem1 > 1.f);
        mem0 = s0 ? 0.f : mem0;
        mem1 = s1 ? 0.f : mem1;
        pm0 = __ballot_sync(0xffffffffu, s0);
        pm1 = __ballot_sync(0xffffffffu, s1);

        // ---- readout state + store (lane 0) ----
        syno2 = fma2g(a_o2, syno2, acco2);
        memo2 = fma2g(b_o2, memo2, mul2(ombo2, syno2));
        if (lane == 0)
            *(float2*)(optr + (size_t)t * (BATCH * OUT_DIM)) =
                make_float2(lo32(memo2), hi32(memo2));
    }
}

// ============================================================
extern "C" void kernel_launch(void* const* d_in, const int* in_sizes, int n_in,
                              void* d_out, int out_size) {
    const float* x  = (const float*)d_in[0];
    const float* Wh = (const float*)d_in[1];
    const float* V  = (const float*)d_in[2];
    const float* Wo = (const float*)d_in[3];
    float* out = (float*)d_out;

    const double S = log1p(exp(1.0));
    const float a_h = expf((float)(-0.004 / (S * 0.01)));
    const float b_h = expf((float)(-0.004 / (S * 0.02)));
    const float a_o = a_h;
    const float b_o = b_h;

    const int smem_bytes = 16 * 16 * 32 * 8 + 8 * 256 * 8;  // 80 KB
    cudaFuncSetAttribute(scan_kernel, cudaFuncAttributeMaxDynamicSharedMemorySize,
                         smem_bytes);

    precompute_inp<<<(T_STEPS * BATCH) / 32, 128>>>(x, Wh);
    scan_kernel<<<BATCH, 32, smem_bytes>>>(V, Wo, out, a_h, b_h, a_o, b_o);
}

// round 6
// speedup vs baseline: 1.9796x; 1.8086x over previous
#include <cuda_runtime.h>
#include <math.h>

#define T_STEPS 4096
#define BATCH   128
#define IN_DIM  96
#define H_DIM   64
#define OUT_DIM 2

typedef unsigned long long ull;

// Precomputed input currents: P[t][b][h] = (t==0 ? 0 : x[t-1,b,:] @ W_h[h,:])
__device__ float g_P[(size_t)T_STEPS * BATCH * H_DIM];

// ---------- packed f32x2 helpers ----------
__device__ __forceinline__ void fma2(ull& d, ull a, ull b) {
    asm("fma.rn.f32x2 %0, %1, %2, %0;" : "+l"(d) : "l"(a), "l"(b));
}
__device__ __forceinline__ ull fma2g(ull a, ull b, ull c) {
    ull d;
    asm("fma.rn.f32x2 %0, %1, %2, %3;" : "=l"(d) : "l"(a), "l"(b), "l"(c));
    return d;
}
__device__ __forceinline__ ull add2(ull a, ull b) {
    ull d;
    asm("add.rn.f32x2 %0, %1, %2;" : "=l"(d) : "l"(a), "l"(b));
    return d;
}
__device__ __forceinline__ ull mul2(ull a, ull b) {
    ull d;
    asm("mul.rn.f32x2 %0, %1, %2;" : "=l"(d) : "l"(a), "l"(b));
    return d;
}
__device__ __forceinline__ ull pack2(float x, float y) {
    ull r;
    asm("mov.b64 %0, {%1, %2};" : "=l"(r) : "f"(x), "f"(y));
    return r;
}
__device__ __forceinline__ float lo32(ull v) { return __uint_as_float((unsigned)v); }
__device__ __forceinline__ float hi32(ull v) { return __uint_as_float((unsigned)(v >> 32)); }

// ============================================================
// Kernel 1: P[g] = (g >= BATCH) ? x[g-BATCH,:] @ W_h.T : 0
// 32 rows x 64 cols per CTA; 128 threads, each 2 rows x 8 cols.
// ============================================================
__global__ __launch_bounds__(128) void precompute_inp(const float* __restrict__ x,
                                                      const float* __restrict__ Wh) {
    __shared__ ull xp[48][34];  // [k-pair][row]
    __shared__ ull wp[48][66];  // [k-pair][col]

    const int tid = threadIdx.x;
    const long long row0 = (long long)blockIdx.x * 32;

    for (int l = tid; l < H_DIM * 48; l += 128) {
        int c = l / 48, kk = l % 48;
        float2 w2 = ((const float2*)(Wh + (size_t)c * IN_DIM))[kk];
        wp[kk][c] = pack2(w2.x, w2.y);
    }
    for (int l = tid; l < 32 * 48; l += 128) {
        int r = l / 48, kk = l % 48;
        long long g = row0 + r;
        float2 v2 = make_float2(0.f, 0.f);
        if (g >= BATCH) v2 = ((const float2*)(x + (g - BATCH) * IN_DIM))[kk];
        xp[kk][r] = pack2(v2.x, v2.y);
    }
    __syncthreads();

    const int tx = tid & 7, ty = tid >> 3;
    const int r0 = ty * 2, c0 = tx * 8;

    ull acc[2][8];
#pragma unroll
    for (int i = 0; i < 2; i++)
#pragma unroll
        for (int j = 0; j < 8; j++) acc[i][j] = 0ull;

#pragma unroll
    for (int kk = 0; kk < 48; kk++) {
        ulonglong2 a  = *(const ulonglong2*)&xp[kk][r0];
        ulonglong2 b0 = *(const ulonglong2*)&wp[kk][c0];
        ulonglong2 b1 = *(const ulonglong2*)&wp[kk][c0 + 2];
        ulonglong2 b2 = *(const ulonglong2*)&wp[kk][c0 + 4];
        ulonglong2 b3 = *(const ulonglong2*)&wp[kk][c0 + 6];
        fma2(acc[0][0], a.x, b0.x); fma2(acc[0][1], a.x, b0.y);
        fma2(acc[0][2], a.x, b1.x); fma2(acc[0][3], a.x, b1.y);
        fma2(acc[0][4], a.x, b2.x); fma2(acc[0][5], a.x, b2.y);
        fma2(acc[0][6], a.x, b3.x); fma2(acc[0][7], a.x, b3.y);
        fma2(acc[1][0], a.y, b0.x); fma2(acc[1][1], a.y, b0.y);
        fma2(acc[1][2], a.y, b1.x); fma2(acc[1][3], a.y, b1.y);
        fma2(acc[1][4], a.y, b2.x); fma2(acc[1][5], a.y, b2.y);
        fma2(acc[1][6], a.y, b3.x); fma2(acc[1][7], a.y, b3.y);
    }

#pragma unroll
    for (int i = 0; i < 2; i++) {
#pragma unroll
        for (int q = 0; q < 2; q++) {
            float4 o;
            o.x = lo32(acc[i][4 * q + 0]) + hi32(acc[i][4 * q + 0]);
            o.y = lo32(acc[i][4 * q + 1]) + hi32(acc[i][4 * q + 1]);
            o.z = lo32(acc[i][4 * q + 2]) + hi32(acc[i][4 * q + 2]);
            o.w = lo32(acc[i][4 * q + 3]) + hi32(acc[i][4 * q + 3]);
            *(float4*)(g_P + (size_t)(row0 + r0 + i) * H_DIM + c0 + 4 * q) = o;
        }
    }
}

// ============================================================
// Kernel 2: sequential scan. ONE WARP per batch. Lane l owns
// neurons 2l, 2l+1. Spikes live in two ballot masks. Recurrent
// dot = fixed-cost nibble-LUT sum (16 LDS.64 + add tree).
// Readout dot = byte-LUT (uniform broadcast LDS).
// Time loop: outer tb += 8, inner fully unrolled -> cur[q]
// statically indexed -> REGISTERS (prefetch truly 8 steps deep).
// ============================================================
__global__ __launch_bounds__(32, 1) void scan_kernel(const float* __restrict__ V,
                                                     const float* __restrict__ Wo,
                                                     float* __restrict__ out,
                                                     float a_h, float b_h,
                                                     float a_o, float b_o) {
    extern __shared__ __align__(16) char smem[];
    float2* lutH = (float2*)smem;                       // [16][16][32] = 64 KB
    float2* lutO = (float2*)(smem + 16 * 16 * 32 * 8);  // [8][256]     = 16 KB

    const int lane = threadIdx.x;
    const int b    = blockIdx.x;

    // ---- build hidden LUT: lutH[p][v][lane] = sum over set bits i of
    //      nibble v of V column j(p,i), for neurons (2*lane, 2*lane+1) ----
#pragma unroll
    for (int p = 0; p < 16; p++) {
        float2 v2[4];
#pragma unroll
        for (int i = 0; i < 4; i++) {
            int j = (p < 8) ? (8 * p + 2 * i) : (8 * (p - 8) + 1 + 2 * i);
            v2[i].x = V[(size_t)(2 * lane) * H_DIM + j];
            v2[i].y = V[(size_t)(2 * lane + 1) * H_DIM + j];
        }
#pragma unroll
        for (int v = 0; v < 16; v++) {
            float2 s = make_float2(0.f, 0.f);
            if (v & 1) { s.x += v2[0].x; s.y += v2[0].y; }
            if (v & 2) { s.x += v2[1].x; s.y += v2[1].y; }
            if (v & 4) { s.x += v2[2].x; s.y += v2[2].y; }
            if (v & 8) { s.x += v2[3].x; s.y += v2[3].y; }
            lutH[(p * 16 + v) * 32 + lane] = s;
        }
    }
    // ---- build readout LUT (byte-indexed, uniform) ----
    for (int idx = lane; idx < 8 * 256; idx += 32) {
        int p = idx >> 8, v = idx & 255;
        float2 s = make_float2(0.f, 0.f);
#pragma unroll
        for (int i = 0; i < 8; i++) {
            if (v & (1 << i)) {
                int j = (p < 4) ? 2 * (8 * p + i) : 2 * (8 * (p - 4) + i) + 1;
                s.x += Wo[j];
                s.y += Wo[H_DIM + j];
            }
        }
        lutO[idx] = s;
    }
    __syncwarp();

    const float omb_h = 1.f - b_h;
    const ull a_h2  = pack2(a_h, a_h);
    const ull a_o2  = pack2(a_o, a_o);
    const ull b_o2  = pack2(b_o, b_o);
    const ull ombo2 = pack2(1.f - b_o, 1.f - b_o);

    ull syn2 = 0ull, syno2 = 0ull, memo2 = 0ull;
    float mem0 = 0.f, mem1 = 0.f;

    const int strideP = BATCH * H_DIM;
    const float* p = g_P + (size_t)b * H_DIM + 2 * lane;
    float2 cur[8];
#pragma unroll
    for (int q = 0; q < 8; q++) cur[q] = *(const float2*)(p + (size_t)q * strideP);
    const float* pf = p + (size_t)8 * strideP;

    float* optr = out + (size_t)b * OUT_DIM;

    unsigned pm0 = 0u, pm1 = 0u;

    for (int tb = 0; tb < T_STEPS; tb += 8) {
#pragma unroll
        for (int q8 = 0; q8 < 8; q8++) {
            const int t = tb + q8;

            // ---- hidden recurrent dot: 16 nibble lookups, fixed cost ----
            ull h[16];
#pragma unroll
            for (int q = 0; q < 8; q++) {
                unsigned v0 = (pm0 >> (4 * q)) & 15u;
                unsigned v1 = (pm1 >> (4 * q)) & 15u;
                h[q]     = *(const ull*)&lutH[(q * 16 + v0) * 32 + lane];
                h[8 + q] = *(const ull*)&lutH[((8 + q) * 16 + v1) * 32 + lane];
            }
#pragma unroll
            for (int st = 8; st >= 1; st >>= 1)
#pragma unroll
                for (int q = 0; q < st; q++) h[q] = add2(h[q], h[q + st]);
            const ull acc2 = h[0];

            // ---- readout dot: 8 byte lookups (broadcast) ----
            ull r[8];
#pragma unroll
            for (int q = 0; q < 4; q++) {
                unsigned u0 = (pm0 >> (8 * q)) & 255u;
                unsigned u1 = (pm1 >> (8 * q)) & 255u;
                r[q]     = *(const ull*)&lutO[q * 256 + u0];
                r[4 + q] = *(const ull*)&lutO[(4 + q) * 256 + u1];
            }
#pragma unroll
            for (int st = 4; st >= 1; st >>= 1)
#pragma unroll
                for (int q = 0; q < st; q++) r[q] = add2(r[q], r[q + st]);
            const ull acco2 = r[0];

            // ---- neuron state update (2 neurons/lane); cur[q8] is a REGISTER ----
            float2 c = cur[q8];
            if (t + 8 < T_STEPS) cur[q8] = *(const float2*)pf;  // prefetch 8 ahead
            pf += strideP;

            syn2 = fma2g(a_h2, syn2, add2(pack2(c.x, c.y), acc2));
            mem0 = fmaf(b_h, mem0, omb_h * lo32(syn2));
            mem1 = fmaf(b_h, mem1, omb_h * hi32(syn2));
            bool s0 = (mem0 > 1.f);
            bool s1 = (mem1 > 1.f);
            mem0 = s0 ? 0.f : mem0;
            mem1 = s1 ? 0.f : mem1;
            pm0 = __ballot_sync(0xffffffffu, s0);
            pm1 = __ballot_sync(0xffffffffu, s1);

            // ---- readout state + store (lane 0) ----
            syno2 = fma2g(a_o2, syno2, acco2);
            memo2 = fma2g(b_o2, memo2, mul2(ombo2, syno2));
            if (lane == 0)
                *(float2*)(optr + (size_t)t * (BATCH * OUT_DIM)) =
                    make_float2(lo32(memo2), hi32(memo2));
        }
    }
}

// ============================================================
extern "C" void kernel_launch(void* const* d_in, const int* in_sizes, int n_in,
                              void* d_out, int out_size) {
    const float* x  = (const float*)d_in[0];
    const float* Wh = (const float*)d_in[1];
    const float* V  = (const float*)d_in[2];
    const float* Wo = (const float*)d_in[3];
    float* out = (float*)d_out;

    const double S = log1p(exp(1.0));
    const float a_h = expf((float)(-0.004 / (S * 0.01)));
    const float b_h = expf((float)(-0.004 / (S * 0.02)));
    const float a_o = a_h;
    const float b_o = b_h;

    const int smem_bytes = 16 * 16 * 32 * 8 + 8 * 256 * 8;  // 80 KB
    cudaFuncSetAttribute(scan_kernel, cudaFuncAttributeMaxDynamicSharedMemorySize,
                         smem_bytes);

    precompute_inp<<<(T_STEPS * BATCH) / 32, 128>>>(x, Wh);
    scan_kernel<<<BATCH, 32, smem_bytes>>>(V, Wo, out, a_h, b_h, a_o, b_o);
}

// round 7
// speedup vs baseline: 2.6083x; 1.3175x over previous
#include <cuda_runtime.h>
#include <math.h>

#define T_STEPS 4096
#define BATCH   128
#define IN_DIM  96
#define H_DIM   64
#define OUT_DIM 2

typedef unsigned long long ull;

// Scratch: input currents P[t][b][h], spike masks M[t][b], readout drives D[t][b]
__device__ float g_P[(size_t)T_STEPS * BATCH * H_DIM];
__device__ ull   g_M[(size_t)T_STEPS * BATCH];
__device__ ull   g_D[(size_t)T_STEPS * BATCH];   // float2 packed

// ---------- packed f32x2 helpers ----------
__device__ __forceinline__ void fma2(ull& d, ull a, ull b) {
    asm("fma.rn.f32x2 %0, %1, %2, %0;" : "+l"(d) : "l"(a), "l"(b));
}
__device__ __forceinline__ ull fma2g(ull a, ull b, ull c) {
    ull d;
    asm("fma.rn.f32x2 %0, %1, %2, %3;" : "=l"(d) : "l"(a), "l"(b), "l"(c));
    return d;
}
__device__ __forceinline__ ull add2(ull a, ull b) {
    ull d;
    asm("add.rn.f32x2 %0, %1, %2;" : "=l"(d) : "l"(a), "l"(b));
    return d;
}
__device__ __forceinline__ ull mul2(ull a, ull b) {
    ull d;
    asm("mul.rn.f32x2 %0, %1, %2;" : "=l"(d) : "l"(a), "l"(b));
    return d;
}
__device__ __forceinline__ ull pack2(float x, float y) {
    ull r;
    asm("mov.b64 %0, {%1, %2};" : "=l"(r) : "f"(x), "f"(y));
    return r;
}
__device__ __forceinline__ float lo32(ull v) { return __uint_as_float((unsigned)v); }
__device__ __forceinline__ float hi32(ull v) { return __uint_as_float((unsigned)(v >> 32)); }

// ============================================================
// Kernel 1: P[g] = (g >= BATCH) ? x[g-BATCH,:] @ W_h.T : 0
// CTA tile 64 rows x 64 cols, 64 threads, thread tile 8x8.
// Per kk: 8 LDS.128 (128B) feeding 64 fma2 -> FMA-bound.
// ============================================================
__global__ __launch_bounds__(64) void precompute_inp(const float* __restrict__ x,
                                                     const float* __restrict__ Wh) {
    __shared__ ull xp[48][64];  // [k-pair][row]
    __shared__ ull wp[48][64];  // [k-pair][col]

    const int tid = threadIdx.x;
    const long long row0 = (long long)blockIdx.x * 64;

    const int fr = tid >> 3;   // 0..7 : row-within-group for fills
    const int fq = tid & 7;    // 0..7 : float4 chunk group (3 chunks each)

    // ---- W fill: wp[kk][c] = (Wh[c][2kk], Wh[c][2kk+1]) ----
#pragma unroll
    for (int rr = 0; rr < 8; rr++) {
        int c = rr * 8 + fr;
        const float4* src = (const float4*)(Wh + (size_t)c * IN_DIM) + fq * 3;
#pragma unroll
        for (int j = 0; j < 3; j++) {
            float4 f = src[j];
            int kk = (fq * 3 + j) * 2;
            *(float2*)&wp[kk][c]     = make_float2(f.x, f.y);
            *(float2*)&wp[kk + 1][c] = make_float2(f.z, f.w);
        }
    }
    // ---- x fill (shifted by one step; t==0 rows are zero) ----
#pragma unroll
    for (int rr = 0; rr < 8; rr++) {
        int r = rr * 8 + fr;
        long long g = row0 + r;
#pragma unroll
        for (int j = 0; j < 3; j++) {
            float4 f = make_float4(0.f, 0.f, 0.f, 0.f);
            if (g >= BATCH)
                f = ((const float4*)(x + (g - BATCH) * IN_DIM))[fq * 3 + j];
            int kk = (fq * 3 + j) * 2;
            *(float2*)&xp[kk][r]     = make_float2(f.x, f.y);
            *(float2*)&xp[kk + 1][r] = make_float2(f.z, f.w);
        }
    }
    __syncthreads();

    const int r0 = (tid & 7) * 8;   // 8 rows
    const int c0 = (tid >> 3) * 8;  // 8 cols

    ull acc[8][8];
#pragma unroll
    for (int i = 0; i < 8; i++)
#pragma unroll
        for (int j = 0; j < 8; j++) acc[i][j] = 0ull;

#pragma unroll 2
    for (int kk = 0; kk < 48; kk++) {
        ulonglong2 A[4], B[4];
#pragma unroll
        for (int j = 0; j < 4; j++) {
            A[j] = *(const ulonglong2*)&xp[kk][r0 + 2 * j];
            B[j] = *(const ulonglong2*)&wp[kk][c0 + 2 * j];
        }
#pragma unroll
        for (int ri = 0; ri < 8; ri++) {
            ull av = (ri & 1) ? A[ri >> 1].y : A[ri >> 1].x;
#pragma unroll
            for (int cj = 0; cj < 4; cj++) {
                fma2(acc[ri][2 * cj],     av, B[cj].x);
                fma2(acc[ri][2 * cj + 1], av, B[cj].y);
            }
        }
    }

#pragma unroll
    for (int ri = 0; ri < 8; ri++) {
        float4 o0, o1;
        o0.x = lo32(acc[ri][0]) + hi32(acc[ri][0]);
        o0.y = lo32(acc[ri][1]) + hi32(acc[ri][1]);
        o0.z = lo32(acc[ri][2]) + hi32(acc[ri][2]);
        o0.w = lo32(acc[ri][3]) + hi32(acc[ri][3]);
        o1.x = lo32(acc[ri][4]) + hi32(acc[ri][4]);
        o1.y = lo32(acc[ri][5]) + hi32(acc[ri][5]);
        o1.z = lo32(acc[ri][6]) + hi32(acc[ri][6]);
        o1.w = lo32(acc[ri][7]) + hi32(acc[ri][7]);
        float* dst = g_P + (size_t)(row0 + r0 + ri) * H_DIM + c0;
        *(float4*)dst       = o0;
        *(float4*)(dst + 4) = o1;
    }
}

// ============================================================
// Kernel 2: hidden-layer scan only. ONE WARP per batch.
// Nibble-LUT recurrent dot; stores produced spike masks to g_M.
// No readout work in the serial loop.
// ============================================================
__global__ __launch_bounds__(32, 1) void scan_kernel(const float* __restrict__ V,
                                                     float a_h, float b_h) {
    extern __shared__ __align__(16) char smem[];
    float2* lutH = (float2*)smem;  // [16][16][32] = 64 KB

    const int lane = threadIdx.x;
    const int b    = blockIdx.x;

    // lutH[p][v][lane] = sum over set bits i of nibble v of V column j(p,i),
    // for neurons (2*lane, 2*lane+1).
#pragma unroll
    for (int p = 0; p < 16; p++) {
        float2 v2[4];
#pragma unroll
        for (int i = 0; i < 4; i++) {
            int j = (p < 8) ? (8 * p + 2 * i) : (8 * (p - 8) + 1 + 2 * i);
            v2[i].x = V[(size_t)(2 * lane) * H_DIM + j];
            v2[i].y = V[(size_t)(2 * lane + 1) * H_DIM + j];
        }
#pragma unroll
        for (int v = 0; v < 16; v++) {
            float2 s = make_float2(0.f, 0.f);
            if (v & 1) { s.x += v2[0].x; s.y += v2[0].y; }
            if (v & 2) { s.x += v2[1].x; s.y += v2[1].y; }
            if (v & 4) { s.x += v2[2].x; s.y += v2[2].y; }
            if (v & 8) { s.x += v2[3].x; s.y += v2[3].y; }
            lutH[(p * 16 + v) * 32 + lane] = s;
        }
    }
    __syncwarp();

    const float omb_h = 1.f - b_h;
    const ull a_h2 = pack2(a_h, a_h);

    ull syn2 = 0ull;
    float mem0 = 0.f, mem1 = 0.f;

    const int strideP = BATCH * H_DIM;
    const float* p = g_P + (size_t)b * H_DIM + 2 * lane;
    float2 cur[8];
#pragma unroll
    for (int q = 0; q < 8; q++) cur[q] = *(const float2*)(p + (size_t)q * strideP);
    const float* pf = p + (size_t)8 * strideP;

    ull* mptr = g_M + b;

    const char* base = smem + lane * 8;
    unsigned pm0 = 0u, pm1 = 0u;

    for (int tb = 0; tb < T_STEPS; tb += 8) {
#pragma unroll
        for (int q8 = 0; q8 < 8; q8++) {
            const int t = tb + q8;

            // 16 nibble lookups, fixed cost
            ull h[16];
#pragma unroll
            for (int q = 0; q < 8; q++) {
                unsigned v0 = ((pm0 >> (4 * q)) & 15u) << 8;
                unsigned v1 = ((pm1 >> (4 * q)) & 15u) << 8;
                h[q]     = *(const ull*)(base + q * 4096 + v0);
                h[8 + q] = *(const ull*)(base + 32768 + q * 4096 + v1);
            }

            // fold input current into a tree leaf (off critical path)
            float2 c = cur[q8];
            if (t + 8 < T_STEPS) cur[q8] = *(const float2*)pf;  // prefetch (register ring)
            pf += strideP;
            h[15] = add2(h[15], pack2(c.x, c.y));

#pragma unroll
            for (int st = 8; st >= 1; st >>= 1)
#pragma unroll
                for (int q = 0; q < st; q++) h[q] = add2(h[q], h[q + st]);

            syn2 = fma2g(a_h2, syn2, h[0]);
            mem0 = fmaf(b_h, mem0, omb_h * lo32(syn2));
            mem1 = fmaf(b_h, mem1, omb_h * hi32(syn2));
            bool s0 = (mem0 > 1.f);
            bool s1 = (mem1 > 1.f);
            mem0 = s0 ? 0.f : mem0;
            mem1 = s1 ? 0.f : mem1;
            pm0 = __ballot_sync(0xffffffffu, s0);
            pm1 = __ballot_sync(0xffffffffu, s1);

            if (lane == 0)
                mptr[(size_t)t * BATCH] = (ull)pm0 | ((ull)pm1 << 32);
        }
    }
}

// ============================================================
// Kernel 3: readout drives D[t][b] = spk_masks[t-1][b] . Wo^T
// (both outputs packed as float2). Fully parallel over (t,b).
// ============================================================
__global__ __launch_bounds__(256) void readout_dots(const float* __restrict__ Wo) {
    __shared__ float2 lutW[256];  // [p(16)][v(16)]

    const int tid = threadIdx.x;
    {
        int p = tid >> 4, v = tid & 15;
        float2 s = make_float2(0.f, 0.f);
#pragma unroll
        for (int i = 0; i < 4; i++) {
            if (v & (1 << i)) {
                int j = (p < 8) ? (8 * p + 2 * i) : (8 * (p - 8) + 1 + 2 * i);
                s.x += Wo[j];
                s.y += Wo[H_DIM + j];
            }
        }
        lutW[tid] = s;
    }
    __syncthreads();

    const size_t idx = (size_t)blockIdx.x * 256 + tid;  // t*BATCH + b
    ull m = (idx >= BATCH) ? g_M[idx - BATCH] : 0ull;
    unsigned p0 = (unsigned)m, p1 = (unsigned)(m >> 32);

    ull r[8];
#pragma unroll
    for (int q = 0; q < 8; q++) {
        unsigned v0 = (p0 >> (4 * q)) & 15u;
        unsigned v1 = (p1 >> (4 * q)) & 15u;
        ull a = *(const ull*)&lutW[q * 16 + v0];
        ull c = *(const ull*)&lutW[(8 + q) * 16 + v1];
        r[q] = add2(a, c);
    }
#pragma unroll
    for (int st = 4; st >= 1; st >>= 1)
#pragma unroll
        for (int q = 0; q < st; q++) r[q] = add2(r[q], r[q + st]);

    g_D[idx] = r[0];
}

// ============================================================
// Kernel 4: readout linear scan. 4 CTAs x 32 threads; thread = batch.
// syn_o[t] = a*syn_o[t-1] + d[t];  mem_o[t] = b*mem_o[t-1] + (1-b)*syn_o[t]
// ============================================================
__global__ __launch_bounds__(32, 1) void readout_scan(float* __restrict__ out,
                                                      float a_o, float b_o) {
    const int b = blockIdx.x * 32 + threadIdx.x;

    const ull a_o2  = pack2(a_o, a_o);
    const ull b_o2  = pack2(b_o, b_o);
    const ull ombo2 = pack2(1.f - b_o, 1.f - b_o);

    ull syno2 = 0ull, memo2 = 0ull;

    const ull* dp = g_D + b;
    ull ring[8];
#pragma unroll
    for (int q = 0; q < 8; q++) ring[q] = dp[(size_t)q * BATCH];
    const ull* pf = dp + (size_t)8 * BATCH;

    ull* optr = (ull*)out + b;  // out[t][b] as float2

    for (int tb = 0; tb < T_STEPS; tb += 8) {
#pragma unroll
        for (int q8 = 0; q8 < 8; q8++) {
            const int t = tb + q8;
            ull d2 = ring[q8];
            if (t + 8 < T_STEPS) ring[q8] = *pf;
            pf += BATCH;
            syno2 = fma2g(a_o2, syno2, d2);
            memo2 = fma2g(b_o2, memo2, mul2(ombo2, syno2));
            optr[(size_t)t * BATCH] = memo2;
        }
    }
}

// ============================================================
extern "C" void kernel_launch(void* const* d_in, const int* in_sizes, int n_in,
                              void* d_out, int out_size) {
    const float* x  = (const float*)d_in[0];
    const float* Wh = (const float*)d_in[1];
    const float* V  = (const float*)d_in[2];
    const float* Wo = (const float*)d_in[3];
    float* out = (float*)d_out;

    const double S = log1p(exp(1.0));
    const float a_h = expf((float)(-0.004 / (S * 0.01)));
    const float b_h = expf((float)(-0.004 / (S * 0.02)));

    const int smem_scan = 16 * 16 * 32 * 8;  // 64 KB
    cudaFuncSetAttribute(scan_kernel, cudaFuncAttributeMaxDynamicSharedMemorySize,
                         smem_scan);

    precompute_inp<<<(T_STEPS * BATCH) / 64, 64>>>(x, Wh);
    scan_kernel<<<BATCH, 32, smem_scan>>>(V, a_h, b_h);
    readout_dots<<<(T_STEPS * BATCH) / 256, 256>>>(Wo);
    readout_scan<<<BATCH / 32, 32>>>(out, a_h, b_h);
}

// round 8
// speedup vs baseline: 3.2045x; 1.2286x over previous
#include <cuda_runtime.h>
#include <math.h>

#define T_STEPS 4096
#define BATCH   128
#define IN_DIM  96
#define H_DIM   64
#define OUT_DIM 2

#define CHUNK   64
#define NCHUNK  (T_STEPS / CHUNK)   // 64

typedef unsigned long long ull;

// Scratch
__device__ float g_P[(size_t)T_STEPS * BATCH * H_DIM];   // input currents
__device__ ull   g_M[(size_t)T_STEPS * BATCH];           // spike masks
__device__ ulonglong2 g_S[NCHUNK * BATCH];               // per-chunk (syn_end, mem_end)
__device__ ulonglong2 g_Pref[NCHUNK * BATCH];            // per-chunk initial (S, M)
__device__ float2 g_tab[CHUNK];                          // (b^{j+1}, g_j)

// ---------- packed f32x2 helpers ----------
__device__ __forceinline__ void fma2(ull& d, ull a, ull b) {
    asm("fma.rn.f32x2 %0, %1, %2, %0;" : "+l"(d) : "l"(a), "l"(b));
}
__device__ __forceinline__ ull fma2g(ull a, ull b, ull c) {
    ull d;
    asm("fma.rn.f32x2 %0, %1, %2, %3;" : "=l"(d) : "l"(a), "l"(b), "l"(c));
    return d;
}
__device__ __forceinline__ ull add2(ull a, ull b) {
    ull d;
    asm("add.rn.f32x2 %0, %1, %2;" : "=l"(d) : "l"(a), "l"(b));
    return d;
}
__device__ __forceinline__ ull mul2(ull a, ull b) {
    ull d;
    asm("mul.rn.f32x2 %0, %1, %2;" : "=l"(d) : "l"(a), "l"(b));
    return d;
}
__device__ __forceinline__ ull pack2(float x, float y) {
    ull r;
    asm("mov.b64 %0, {%1, %2};" : "=l"(r) : "f"(x), "f"(y));
    return r;
}
__device__ __forceinline__ float lo32(ull v) { return __uint_as_float((unsigned)v); }
__device__ __forceinline__ float hi32(ull v) { return __uint_as_float((unsigned)(v >> 32)); }

__device__ __forceinline__ unsigned smem_u32(const void* p) {
    unsigned a;
    asm("{ .reg .u64 t; cvta.to.shared.u64 t, %1; cvt.u32.u64 %0, t; }" : "=r"(a) : "l"(p));
    return a;
}
__device__ __forceinline__ ull lds_u64(unsigned a) {
    ull v;
    asm("ld.shared.b64 %0, [%1];" : "=l"(v) : "r"(a));
    return v;
}

// ============================================================
// Kernel 1: P[g] = (g >= BATCH) ? x[g-BATCH,:] @ W_h.T : 0
// CTA tile 64 rows x 64 cols, 64 threads, thread tile 8x8.
// ============================================================
__global__ __launch_bounds__(64) void precompute_inp(const float* __restrict__ x,
                                                     const float* __restrict__ Wh) {
    __shared__ ull xp[48][64];
    __shared__ ull wp[48][64];

    const int tid = threadIdx.x;
    const long long row0 = (long long)blockIdx.x * 64;

    const int fr = tid >> 3;
    const int fq = tid & 7;

#pragma unroll
    for (int rr = 0; rr < 8; rr++) {
        int c = rr * 8 + fr;
        const float4* src = (const float4*)(Wh + (size_t)c * IN_DIM) + fq * 3;
#pragma unroll
        for (int j = 0; j < 3; j++) {
            float4 f = src[j];
            int kk = (fq * 3 + j) * 2;
            *(float2*)&wp[kk][c]     = make_float2(f.x, f.y);
            *(float2*)&wp[kk + 1][c] = make_float2(f.z, f.w);
        }
    }
#pragma unroll
    for (int rr = 0; rr < 8; rr++) {
        int r = rr * 8 + fr;
        long long g = row0 + r;
#pragma unroll
        for (int j = 0; j < 3; j++) {
            float4 f = make_float4(0.f, 0.f, 0.f, 0.f);
            if (g >= BATCH)
                f = ((const float4*)(x + (g - BATCH) * IN_DIM))[fq * 3 + j];
            int kk = (fq * 3 + j) * 2;
            *(float2*)&xp[kk][r]     = make_float2(f.x, f.y);
            *(float2*)&xp[kk + 1][r] = make_float2(f.z, f.w);
        }
    }
    __syncthreads();

    const int r0 = (tid & 7) * 8;
    const int c0 = (tid >> 3) * 8;

    ull acc[8][8];
#pragma unroll
    for (int i = 0; i < 8; i++)
#pragma unroll
        for (int j = 0; j < 8; j++) acc[i][j] = 0ull;

#pragma unroll 2
    for (int kk = 0; kk < 48; kk++) {
        ulonglong2 A[4], B[4];
#pragma unroll
        for (int j = 0; j < 4; j++) {
            A[j] = *(const ulonglong2*)&xp[kk][r0 + 2 * j];
            B[j] = *(const ulonglong2*)&wp[kk][c0 + 2 * j];
        }
#pragma unroll
        for (int ri = 0; ri < 8; ri++) {
            ull av = (ri & 1) ? A[ri >> 1].y : A[ri >> 1].x;
#pragma unroll
            for (int cj = 0; cj < 4; cj++) {
                fma2(acc[ri][2 * cj],     av, B[cj].x);
                fma2(acc[ri][2 * cj + 1], av, B[cj].y);
            }
        }
    }

#pragma unroll
    for (int ri = 0; ri < 8; ri++) {
        float4 o0, o1;
        o0.x = lo32(acc[ri][0]) + hi32(acc[ri][0]);
        o0.y = lo32(acc[ri][1]) + hi32(acc[ri][1]);
        o0.z = lo32(acc[ri][2]) + hi32(acc[ri][2]);
        o0.w = lo32(acc[ri][3]) + hi32(acc[ri][3]);
        o1.x = lo32(acc[ri][4]) + hi32(acc[ri][4]);
        o1.y = lo32(acc[ri][5]) + hi32(acc[ri][5]);
        o1.z = lo32(acc[ri][6]) + hi32(acc[ri][6]);
        o1.w = lo32(acc[ri][7]) + hi32(acc[ri][7]);
        float* dst = g_P + (size_t)(row0 + r0 + ri) * H_DIM + c0;
        *(float4*)dst       = o0;
        *(float4*)(dst + 4) = o1;
    }
}

// ============================================================
// Kernel 2: hidden scan, one warp per batch, 6-bit-group LUT.
// lut[p][v][lane] (p=0..11, v=0..63): sum over set bits i of v
// of V columns j(p,i) for neurons (2*lane, 2*lane+1).
//   p in 0..5  -> pm0 bits 6p..6p+5, neurons j = 12p + 2i
//   p in 6..11 -> pm1 bits 6p'..6p'+5, neurons j = 12p' + 2i + 1
// LUT base aligned to 16KB so lookup addr = SHF + LOP3(and-or).
// ============================================================
__global__ __launch_bounds__(32, 1) void scan_kernel(const float* __restrict__ V,
                                                     float a_h, float b_h) {
    extern __shared__ __align__(16) char smem[];

    const int lane = threadIdx.x;
    const int b    = blockIdx.x;

    const unsigned raw32  = smem_u32(smem);
    const unsigned abase  = (raw32 + 16383u) & ~16383u;   // 16KB-aligned
    char* ab = smem + (abase - raw32);

    // ---- build LUT (each lane builds only its own lane slots) ----
    for (int p = 0; p < 12; p++) {
        char* bpp = ab + p * 16384 + lane * 8;
        *(float2*)bpp = make_float2(0.f, 0.f);
        int pm = (p < 6) ? p : p - 6;
#pragma unroll
        for (int i = 0; i < 6; i++) {
            int l = 6 * pm + i;
            float2 c = make_float2(0.f, 0.f);
            if (l < 32) {
                int j = (p < 6) ? 2 * l : 2 * l + 1;
                c.x = V[(size_t)(2 * lane) * H_DIM + j];
                c.y = V[(size_t)(2 * lane + 1) * H_DIM + j];
            }
            *(float2*)(bpp + (1u << i) * 256) = c;
        }
        for (int v = 3; v < 64; v++) {
            if ((v & (v - 1)) == 0) continue;
            float2 e1 = *(const float2*)(bpp + (v & (v - 1)) * 256);
            float2 e2 = *(const float2*)(bpp + (v & (-v)) * 256);
            *(float2*)(bpp + v * 256) = make_float2(e1.x + e2.x, e1.y + e2.y);
        }
    }
    __syncwarp();

    // per-position base addresses (bits 8..13 clear; lane in bits 3..7)
    unsigned bp[12];
#pragma unroll
    for (int p = 0; p < 12; p++) bp[p] = abase + p * 16384 + lane * 8;

    const float omb_h = 1.f - b_h;
    const ull a_h2 = pack2(a_h, a_h);
    const ull omb2 = pack2(omb_h, omb_h);
    const ull b_h2 = pack2(b_h, b_h);

    ull syn2 = 0ull, mem2 = 0ull;

    const int strideP = BATCH * H_DIM;
    const float* p = g_P + (size_t)b * H_DIM + 2 * lane;
    float2 cur[8];
#pragma unroll
    for (int q = 0; q < 8; q++) cur[q] = *(const float2*)(p + (size_t)q * strideP);
    const float* pf = p + (size_t)8 * strideP;

    ull* mptr = g_M + b;
    unsigned pm0 = 0u, pm1 = 0u;
    const unsigned M6 = 0x3F00u;

    for (int tb = 0; tb < T_STEPS; tb += 8) {
#pragma unroll
        for (int q8 = 0; q8 < 8; q8++) {
            const int t = tb + q8;

            ull h0 = lds_u64(((pm0 << 8)  & M6) | bp[0]);
            ull h1 = lds_u64(((pm0 << 2)  & M6) | bp[1]);
            ull h2 = lds_u64(((pm0 >> 4)  & M6) | bp[2]);
            ull h3 = lds_u64(((pm0 >> 10) & M6) | bp[3]);
            ull h4 = lds_u64(((pm0 >> 16) & M6) | bp[4]);
            ull h5 = lds_u64(((pm0 >> 22) & M6) | bp[5]);
            ull h6 = lds_u64(((pm1 << 8)  & M6) | bp[6]);
            ull h7 = lds_u64(((pm1 << 2)  & M6) | bp[7]);
            ull h8 = lds_u64(((pm1 >> 4)  & M6) | bp[8]);
            ull h9 = lds_u64(((pm1 >> 10) & M6) | bp[9]);
            ull hA = lds_u64(((pm1 >> 16) & M6) | bp[10]);
            ull hB = lds_u64(((pm1 >> 22) & M6) | bp[11]);

            float2 c = cur[q8];
            if (t + 8 < T_STEPS) cur[q8] = *(const float2*)pf;  // register ring prefetch
            pf += strideP;

            ull s01 = add2(h0, h1);
            ull s23 = add2(h2, h3);
            ull s45 = add2(h4, h5);
            ull s67 = add2(h6, h7);
            ull s89 = add2(h8, h9);
            ull sAB = add2(hA, hB);
            ull sA4 = add2(s01, s23);
            ull sB4 = add2(s45, s67);
            ull sC4 = add2(s89, sAB);
            ull sD4 = add2(pack2(c.x, c.y), sA4);
            ull tot = add2(add2(sB4, sC4), sD4);

            syn2 = fma2g(a_h2, syn2, tot);
            mem2 = fma2g(b_h2, mem2, mul2(omb2, syn2));
            float m0 = lo32(mem2), m1 = hi32(mem2);
            bool s0 = (m0 > 1.f);
            bool s1 = (m1 > 1.f);
            m0 = s0 ? 0.f : m0;
            m1 = s1 ? 0.f : m1;
            mem2 = pack2(m0, m1);
            pm0 = __ballot_sync(0xffffffffu, s0);
            pm1 = __ballot_sync(0xffffffffu, s1);

            if (lane == 0)
                mptr[(size_t)t * BATCH] = (ull)pm0 | ((ull)pm1 << 32);
        }
    }
}

// ============================================================
// Kernel 3 (R1): per-chunk local readout scans from masks.
// Grid = NCHUNK CTAs x 128 threads (thread = batch). Writes
// provisional mem_o to out and (syn_end, mem_end) to g_S.
// ============================================================
__global__ __launch_bounds__(128) void readout_chunks(const float* __restrict__ Wo,
                                                      float* __restrict__ out,
                                                      float a_o, float b_o) {
    __shared__ float2 lutOb[8 * 256];  // byte LUT, 16 KB

    const int tid = threadIdx.x;
    const int c   = blockIdx.x;

    for (int idx = tid; idx < 8 * 256; idx += 128) {
        int pp = idx >> 8, v = idx & 255;
        float2 s = make_float2(0.f, 0.f);
#pragma unroll
        for (int i = 0; i < 8; i++) {
            if (v & (1 << i)) {
                int j = (pp < 4) ? 2 * (8 * pp + i) : 2 * (8 * (pp - 4) + i) + 1;
                s.x += Wo[j];
                s.y += Wo[H_DIM + j];
            }
        }
        lutOb[idx] = s;
    }
    __syncthreads();

    const int b = tid;
    const ull a_o2  = pack2(a_o, a_o);
    const ull b_o2  = pack2(b_o, b_o);
    const ull ombo2 = pack2(1.f - b_o, 1.f - b_o);

    ull syno2 = 0ull, memo2 = 0ull;

    // mask ring: need g_M[(c*64 - 1 + j)*B + b]
    const ull* mp = g_M + ((long long)c * CHUNK - 1) * BATCH + b;
    ull ring[8];
#pragma unroll
    for (int q = 0; q < 8; q++)
        ring[q] = (c == 0 && q == 0) ? 0ull : mp[(size_t)q * BATCH];
    const ull* pfm = mp + (size_t)8 * BATCH;

    ull* optr = (ull*)out + (size_t)c * CHUNK * BATCH + b;

    for (int jb = 0; jb < CHUNK; jb += 8) {
#pragma unroll
        for (int q8 = 0; q8 < 8; q8++) {
            const int j = jb + q8;
            ull m = ring[q8];
            if (j + 8 < CHUNK) ring[q8] = *pfm;
            pfm += BATCH;

            unsigned p0 = (unsigned)m, p1 = (unsigned)(m >> 32);
            ull r0 = add2(*(const ull*)&lutOb[0 * 256 + (p0 & 255u)],
                          *(const ull*)&lutOb[4 * 256 + (p1 & 255u)]);
            ull r1 = add2(*(const ull*)&lutOb[1 * 256 + ((p0 >> 8) & 255u)],
                          *(const ull*)&lutOb[5 * 256 + ((p1 >> 8) & 255u)]);
            ull r2 = add2(*(const ull*)&lutOb[2 * 256 + ((p0 >> 16) & 255u)],
                          *(const ull*)&lutOb[6 * 256 + ((p1 >> 16) & 255u)]);
            ull r3 = add2(*(const ull*)&lutOb[3 * 256 + (p0 >> 24)],
                          *(const ull*)&lutOb[7 * 256 + (p1 >> 24)]);
            ull d2 = add2(add2(r0, r1), add2(r2, r3));

            syno2 = fma2g(a_o2, syno2, d2);
            memo2 = fma2g(b_o2, memo2, mul2(ombo2, syno2));
            optr[(size_t)j * BATCH] = memo2;
        }
    }
    g_S[c * BATCH + b] = make_ulonglong2(syno2, memo2);
}

// ============================================================
// Kernel 4 (R2): chunk prefix + fixup tables. 1 CTA x 128 thr.
// ============================================================
__global__ __launch_bounds__(128) void readout_prefix(float a_o, float b_o) {
    const int b = threadIdx.x;

    // tables: tab[j] = (b^{j+1}, g_j), g_j = b*g_{j-1} + (1-b)*a^{j+1}
    float ap = a_o, bpw = b_o, g = (1.f - b_o) * a_o;
    float a64 = 0.f, b64 = 0.f, g63 = 0.f;
    for (int j = 0; j < CHUNK; j++) {
        if (b == 0) g_tab[j] = make_float2(bpw, g);
        if (j == CHUNK - 1) { a64 = ap; b64 = bpw; g63 = g; }
        ap *= a_o;
        bpw *= b_o;
        g = b_o * g + (1.f - b_o) * ap;
    }

    const ull a64_2 = pack2(a64, a64);
    const ull b64_2 = pack2(b64, b64);
    const ull g63_2 = pack2(g63, g63);

    ull S = 0ull, M = 0ull;
    for (int c = 0; c < NCHUNK; c++) {
        g_Pref[c * BATCH + b] = make_ulonglong2(S, M);
        ulonglong2 sm = g_S[c * BATCH + b];
        ull Sold = S;
        S = fma2g(a64_2, S, sm.x);
        M = add2(fma2g(b64_2, M, sm.y), mul2(g63_2, Sold));
    }
}

// ============================================================
// Kernel 5 (R3): fixup: out[t][b] += b^{j+1}*M_c + g_j*S_c
// ============================================================
__global__ __launch_bounds__(256) void readout_fix(float* __restrict__ out) {
    const size_t idx = (size_t)blockIdx.x * 256 + threadIdx.x;  // t*BATCH + b
    const int t = (int)(idx >> 7);
    const int b = (int)(idx & 127);
    const int c = t >> 6;
    const int j = t & 63;

    float2 tab = g_tab[j];
    ulonglong2 pref = g_Pref[c * BATCH + b];
    ull fix = add2(mul2(pack2(tab.x, tab.x), pref.y),
                   mul2(pack2(tab.y, tab.y), pref.x));
    ull* o = (ull*)out + idx;
    *o = add2(*o, fix);
}

// ============================================================
extern "C" void kernel_launch(void* const* d_in, const int* in_sizes, int n_in,
                              void* d_out, int out_size) {
    const float* x  = (const float*)d_in[0];
    const float* Wh = (const float*)d_in[1];
    const float* V  = (const float*)d_in[2];
    const float* Wo = (const float*)d_in[3];
    float* out = (float*)d_out;

    const double S = log1p(exp(1.0));
    const float a_h = expf((float)(-0.004 / (S * 0.01)));
    const float b_h = expf((float)(-0.004 / (S * 0.02)));

    const int smem_scan = 12 * 16384 + 16384;  // 208 KB (incl. alignment pad)
    cudaFuncSetAttribute(scan_kernel, cudaFuncAttributeMaxDynamicSharedMemorySize,
                         smem_scan);

    precompute_inp<<<(T_STEPS * BATCH) / 64, 64>>>(x, Wh);
    scan_kernel<<<BATCH, 32, smem_scan>>>(V, a_h, b_h);
    readout_chunks<<<NCHUNK, 128>>>(Wo, out, a_h, b_h);
    readout_prefix<<<1, 128>>>(a_h, b_h);
    readout_fix<<<(T_STEPS * BATCH) / 256, 256>>>(out);
}